// round 12
// baseline (speedup 1.0000x reference)
#include <cuda_runtime.h>
#include <cstdint>

// Shape (fixed by setup_inputs): B=64, T=2000, V=256, S=200, L=401
#define NEG2 -1e30f
#define VDIM 256
#define BMAX 64
#define NWIN 3                // 2-step windows per barrier block
#define ROWSPB 6              // rows consumed per barrier block
#define GHOSTL 3              // ghost lanes per warp (1 lane corrupted / window)
#define LPW 29                // real lanes per warp
#define NTHR 256              // 8 warps: warps 0-3 row A, warps 4-7 row B
#define NSTAGE 32             // cp.async ring stages per row
#define NALPHA 32             // alpha blocks (2 rows each)
#define INVLN2 1.4426950408889634f
#define LN2F   0.6931471805599453f

// Dynamic shared layout (floats):
//   [0, 2*NSTAGE*VDIM)                : row rings, half h at h*NSTAGE*VDIM
//   then halo: 2 halves * 2 par * 4 warps * GHOSTL float4
//   then fin:  2 halves * 2 floats
//   (lse blocks reuse the halo region for partial sums)
#define ROWF   (NSTAGE * VDIM)
#define HALOF  (2 * 2 * 4 * GHOSTL * 4)
#define OFF_HALO (2 * ROWF)
#define OFF_FIN  (OFF_HALO + HALOF)
#define SMEM_FLOATS (OFF_FIN + 8)
#define SMEM_BYTES  (SMEM_FLOATS * 4)

// Cross-block scratch (device globals: no allocation).
__device__ float g_lsesum[BMAX];
__device__ int   g_flag[BMAX];

__device__ __forceinline__ float ex2f(float x) {
    float y; asm("ex2.approx.f32 %0, %1;" : "=f"(y) : "f"(x)); return y;
}
__device__ __forceinline__ float lg2f(float x) {
    float y; asm("lg2.approx.f32 %0, %1;" : "=f"(y) : "f"(x)); return y;
}

// Composed 2-step CTC window update (log2 domain), 2 pairs per thread.
// Common-max + gated-partial-sum form: 13 ex2 + 4 lg2.
__device__ __forceinline__ void window_update(
    float& B0, float& L0, float& B1, float& L1,
    float b0, float b1, float el0, float el1, float eh0, float eh1, float em0,
    float emax, float g_lo, float g_hi, float g_m1, int lane)
{
    float Lm1 = __shfl_up_sync(0xFFFFFFFFu, L1, 1);
    float Bm1 = __shfl_up_sync(0xFFFFFFFFu, B1, 1);
    float Lm2 = __shfl_up_sync(0xFFFFFFFFu, L0, 1);
    if (lane == 0) { Lm1 = NEG2; Bm1 = NEG2; Lm2 = NEG2; }

    float amax = fmaxf(fmaxf(fmaxf(B0, L0), fmaxf(B1, L1)),
                       fmaxf(fmaxf(Lm1, Bm1), Lm2));
    float M = fmaxf(amax, -1e30f) + emax;

    float e_x1 = ex2f(B0  + b0  - M);
    float e_x2 = ex2f(Lm1 + b0  - M);
    float e_x3 = ex2f(Lm1 + em0 - M);
    float e_x4 = ex2f(Bm1 + em0 - M);
    float e_x5 = ex2f(Lm2 + em0 - M) * g_m1;
    float e_y1 = ex2f(L0  + el0 - M);
    float e_y2 = ex2f(B0  + el0 - M);
    float e_y3 = ex2f(Lm1 + el0 - M) * g_lo;
    float e_z1 = ex2f(B1  + b0  - M);
    float e_z2 = ex2f(L0  + b0  - M);
    float e_u1 = ex2f(L1  + eh0 - M);
    float e_u2 = ex2f(B1  + eh0 - M);
    float e_u3 = ex2f(L0  + eh0 - M) * g_hi;

    float Q   = e_x3 + e_x4 + e_x5;
    float x12 = e_x1 + e_x2;
    float yy  = e_y1 + e_y2;
    float Ys  = yy + e_y3;
    float z12 = e_z1 + e_z2;

    float sB0 = x12 + Q;
    float sL0 = Ys + x12 + g_lo * Q;
    float sB1 = z12 + Ys;
    float sL1 = e_u1 + e_u2 + e_u3 + z12 + g_hi * Ys;

    B0 = M + lg2f(sB0) + b1;
    L0 = M + lg2f(sL0) + el1;
    B1 = M + lg2f(sB1) + b1;
    L1 = M + lg2f(sL1) + eh1;
}

// ---------------------------------------------------------------------------
// Fused kernel: blocks [0,32) = alpha (2 rows/block, 4 warps per row);
// blocks [32,96) = per-row LSE sums (8 warps).
// ---------------------------------------------------------------------------
__global__ __launch_bounds__(NTHR, 1)
void ctc_fused_kernel(const float* __restrict__ logits,
                      const int*  __restrict__ targets,
                      const int*  __restrict__ logits_lengths,
                      const int*  __restrict__ targets_lengths,
                      float* __restrict__ out,
                      int T, int S)
{
    extern __shared__ float smem[];
    const int tid  = threadIdx.x;
    const int lane = tid & 31;
    const int w    = tid >> 5;

    if (blockIdx.x >= NALPHA) {
        // ================= LSE block (one row, 8 warps) =================
        const int b   = blockIdx.x - NALPHA;
        const int len = __ldg(&logits_lengths[b]);
        const float* __restrict__ rowp = logits + (size_t)b * T * VDIM;
        float* sh_part = smem + OFF_HALO;
        float acc = 0.0f;
        for (int t = w; t < len; t += 8) {
            const float4* r4 = reinterpret_cast<const float4*>(rowp + (size_t)t * VDIM);
            float4 a = r4[lane], c = r4[lane + 32];
            float s = __expf(a.x)+__expf(a.y)+__expf(a.z)+__expf(a.w)
                    + __expf(c.x)+__expf(c.y)+__expf(c.z)+__expf(c.w);
            #pragma unroll
            for (int o = 16; o; o >>= 1) s += __shfl_xor_sync(0xFFFFFFFFu, s, o);
            if (lane == 0) acc += __logf(s);
        }
        if (lane == 0) sh_part[w] = acc;
        __syncthreads();
        if (tid == 0) {
            float s = 0.0f;
            #pragma unroll
            for (int k = 0; k < 8; ++k) s += sh_part[k];
            g_lsesum[b] = s;
            __threadfence();
            g_flag[b] = 1;
        }
        return;
    }

    // ================= alpha block: 2 rows =================
    const int half = w >> 2;                 // 0: warps 0-3, 1: warps 4-7
    const int wh   = w & 3;                  // warp index within half
    const int htid = tid & 127;              // thread index within half
    const int b    = 2 * blockIdx.x + half;  // batch row for this half

    float* sh_rowh = smem + half * ROWF;                       // [NSTAGE][VDIM]
    float4* sh_halo = reinterpret_cast<float4*>(smem + OFF_HALO)
                    + half * (2 * 4 * GHOSTL);                 // [par][4][GHOSTL]
    float* sh_fin = smem + OFF_FIN + half * 2;

    const int plo = 2 * (wh * LPW + lane - GHOSTL);
    const int phi = plo + 1;
    const bool realln = (lane >= GHOSTL);

    int lblo = 0, lbhi = 0, sklo = 0, skhi = 0;
    if (plo >= 0 && plo < S) {
        lblo = __ldg(&targets[b * S + plo]);
        if (plo >= 1) sklo = (lblo != __ldg(&targets[b * S + plo - 1]));
    }
    if (phi >= 0 && phi < S) {
        lbhi = __ldg(&targets[b * S + phi]);
        skhi = (lbhi != __ldg(&targets[b * S + phi - 1]));
    }
    const float g_lo = sklo ? 1.0f : 0.0f;
    const float g_hi = skhi ? 1.0f : 0.0f;
    float g_m1 = __shfl_up_sync(0xFFFFFFFFu, g_hi, 1);
    if (lane == 0) g_m1 = 0.0f;
    const float pen_lo = sklo ? 0.0f : NEG2;
    const float pen_hi = skhi ? 0.0f : NEG2;

    float B0 = (plo == 0) ? 0.0f : NEG2, L0 = NEG2, B1 = NEG2, L1 = NEG2;

    if (lane >= 32 - GHOSTL)
        sh_halo[0 * (4 * GHOSTL) + wh * GHOSTL + (lane - (32 - GHOSTL))] =
            make_float4(B0, L0, B1, L1);

    const int len = __ldg(&logits_lengths[b]);
    const int W   = len >> 1;
    const int odd = len & 1;
    // Both halves must iterate the same block count (shared __syncthreads).
    const int lenA = __ldg(&logits_lengths[2 * blockIdx.x]);
    const int lenB = __ldg(&logits_lengths[2 * blockIdx.x + 1]);
    const int Wmax = max(lenA, lenB) >> 1;
    const int nblk = (Wmax + NWIN - 1) / NWIN;

    const float* __restrict__ rowp = logits + (size_t)b * T * VDIM;
    uint32_t s_base = (uint32_t)__cvta_generic_to_shared(sh_rowh);

    // Prologue: stage rows 0..11 (2 groups of 6); len >= 1500 so all valid.
    {
        #pragma unroll
        for (int g = 0; g < 2; ++g) {
            #pragma unroll
            for (int i = 0; i < ROWSPB; ++i) {
                int st = g * ROWSPB + i;
                uint32_t dst = s_base + (uint32_t)(st * VDIM * 4 + htid * 8);
                const float* src = rowp + (size_t)st * VDIM + htid * 2;
                asm volatile("cp.async.ca.shared.global [%0], [%1], 8;\n"
                             :: "r"(dst), "l"(src));
            }
            asm volatile("cp.async.commit_group;\n");
        }
        asm volatile("cp.async.wait_group 0;\n" ::: "memory");
    }
    __syncthreads();

    // Emissions for block 0 (windows 0..2), log2 units, + per-window emax.
    float cb0[NWIN], cb1[NWIN], cl0[NWIN], cl1[NWIN], ch0[NWIN], ch1[NWIN],
          cm0[NWIN], cmx[NWIN];
    #pragma unroll
    for (int i = 0; i < NWIN; ++i) {
        const float* r0 = sh_rowh + (2 * i) * VDIM;
        const float* r1 = sh_rowh + (2 * i + 1) * VDIM;
        cb0[i] = r0[0]    * INVLN2;  cb1[i] = r1[0]    * INVLN2;
        cl0[i] = r0[lblo] * INVLN2;  cl1[i] = r1[lblo] * INVLN2;
        ch0[i] = r0[lbhi] * INVLN2;  ch1[i] = r1[lbhi] * INVLN2;
        cm0[i] = __shfl_up_sync(0xFFFFFFFFu, ch0[i], 1);
        cmx[i] = fmaxf(fmaxf(cb0[i], cl0[i]), fmaxf(ch0[i], cm0[i]));
    }

    int par = 0;
    for (int blk = 0; blk < nblk; ++blk) {
        const int tb = blk * ROWSPB;

        // Stage rows tb+12..tb+17 for this half's row; resident through tb+11.
        {
            #pragma unroll
            for (int i = 0; i < ROWSPB; ++i) {
                const int tn = tb + 12 + i;
                if (tn < len) {
                    uint32_t dst = s_base +
                        (uint32_t)((tn & (NSTAGE - 1)) * VDIM * 4 + htid * 8);
                    const float* src = rowp + (size_t)tn * VDIM + htid * 2;
                    asm volatile("cp.async.ca.shared.global [%0], [%1], 8;\n"
                                 :: "r"(dst), "l"(src));
                }
            }
            asm volatile("cp.async.commit_group;\n");
            asm volatile("cp.async.wait_group 1;\n" ::: "memory");
        }
        __syncthreads();

        if (lane < GHOSTL && wh > 0) {
            float4 h = sh_halo[par * (4 * GHOSTL) + (wh - 1) * GHOSTL + lane];
            B0 = h.x; L0 = h.y; B1 = h.z; L1 = h.w;
        }

        // Gather next block's emissions (rows tb+6..tb+11).
        float nb0[NWIN], nb1[NWIN], nl0[NWIN], nl1[NWIN], nh0[NWIN], nh1[NWIN],
              nm0[NWIN], nmx[NWIN];
        #pragma unroll
        for (int i = 0; i < NWIN; ++i) {
            const int r0i = min(tb + ROWSPB + 2 * i,     len - 1);
            const int r1i = min(tb + ROWSPB + 2 * i + 1, len - 1);
            const float* r0 = sh_rowh + (r0i & (NSTAGE - 1)) * VDIM;
            const float* r1 = sh_rowh + (r1i & (NSTAGE - 1)) * VDIM;
            nb0[i] = r0[0]    * INVLN2;  nb1[i] = r1[0]    * INVLN2;
            nl0[i] = r0[lblo] * INVLN2;  nl1[i] = r1[lblo] * INVLN2;
            nh0[i] = r0[lbhi] * INVLN2;  nh1[i] = r1[lbhi] * INVLN2;
            nm0[i] = __shfl_up_sync(0xFFFFFFFFu, nh0[i], 1);
            nmx[i] = fmaxf(fmaxf(nb0[i], nl0[i]), fmaxf(nh0[i], nm0[i]));
        }

        const int wbase = blk * NWIN;
        if (wbase + NWIN <= W) {
            #pragma unroll
            for (int i = 0; i < NWIN; ++i)
                window_update(B0, L0, B1, L1, cb0[i], cb1[i], cl0[i], cl1[i],
                              ch0[i], ch1[i], cm0[i], cmx[i],
                              g_lo, g_hi, g_m1, lane);
        } else {
            #pragma unroll
            for (int i = 0; i < NWIN; ++i) {
                float tB0 = B0, tL0 = L0, tB1 = B1, tL1 = L1;
                window_update(tB0, tL0, tB1, tL1, cb0[i], cb1[i], cl0[i], cl1[i],
                              ch0[i], ch1[i], cm0[i], cmx[i],
                              g_lo, g_hi, g_m1, lane);
                const bool act = (wbase + i) < W;
                B0 = act ? tB0 : B0;  L0 = act ? tL0 : L0;
                B1 = act ? tB1 : B1;  L1 = act ? tL1 : L1;
            }
        }

        if (lane >= 32 - GHOSTL)
            sh_halo[(par ^ 1) * (4 * GHOSTL) + wh * GHOSTL + (lane - (32 - GHOSTL))] =
                make_float4(B0, L0, B1, L1);
        par ^= 1;

        #pragma unroll
        for (int i = 0; i < NWIN; ++i) {
            cb0[i] = nb0[i]; cb1[i] = nb1[i]; cl0[i] = nl0[i]; cl1[i] = nl1[i];
            ch0[i] = nh0[i]; ch1[i] = nh1[i]; cm0[i] = nm0[i]; cmx[i] = nmx[i];
        }
    }

    __syncthreads();   // final halo stores visible

    if (odd) {
        // One plain step for t = len-1 for this half.
        if (lane < GHOSTL && wh > 0) {
            float4 h = sh_halo[par * (4 * GHOSTL) + (wh - 1) * GHOSTL + lane];
            B0 = h.x; L0 = h.y; B1 = h.z; L1 = h.w;
        }
        const float* rr = sh_rowh + ((len - 1) & (NSTAGE - 1)) * VDIM;
        const float eb = rr[0]    * INVLN2;
        const float el = rr[lblo] * INVLN2;
        const float eh = rr[lbhi] * INVLN2;

        float pL = __shfl_up_sync(0xFFFFFFFFu, L1, 1);
        if (lane == 0) pL = NEG2;

        float m0  = fmaxf(fmaxf(B0, pL), -1e30f);
        float nB0 = m0 + lg2f(ex2f(B0 - m0) + ex2f(pL - m0)) + eb;
        float t3  = pL + pen_lo;
        float m1  = fmaxf(fmaxf(fmaxf(L0, B0), t3), -1e30f);
        float nL0 = m1 + lg2f(ex2f(L0 - m1) + ex2f(B0 - m1) + ex2f(t3 - m1)) + el;

        float m2  = fmaxf(fmaxf(B1, L0), -1e30f);
        float nB1 = m2 + lg2f(ex2f(B1 - m2) + ex2f(L0 - m2)) + eb;
        float t3h = L0 + pen_hi;
        float m3  = fmaxf(fmaxf(fmaxf(L1, B1), t3h), -1e30f);
        float nL1 = m3 + lg2f(ex2f(L1 - m3) + ex2f(B1 - m3) + ex2f(t3h - m3)) + eh;

        B0 = nB0; L0 = nL0; B1 = nB1; L1 = nL1;
    }

    // ---- epilogue (per half) ----
    const int tl = __ldg(&targets_lengths[b]);
    if (realln) {
        if (plo == tl - 1) sh_fin[0] = L0;   // state 2*tl - 1
        if (phi == tl - 1) sh_fin[0] = L1;
        if (plo == tl)     sh_fin[1] = B0;   // state 2*tl
        if (phi == tl)     sh_fin[1] = B1;
    }
    __syncthreads();

    if (htid == 0) {
        while (((volatile int*)g_flag)[b] == 0) { }
        const float ls = *((volatile float*)&g_lsesum[b]);
        const float f1 = sh_fin[0], f2 = sh_fin[1];   // log2 units
        const float mm = fmaxf(fmaxf(f1, f2), -1e30f);
        const float lae = mm + lg2f(ex2f(f1 - mm) + ex2f(f2 - mm));
        out[b] = ls - LN2F * lae;
    }
}

// ---------------------------------------------------------------------------
// Launch: 96 blocks (32 alpha x 2 rows + 64 lse), dynamic smem.
// ---------------------------------------------------------------------------
extern "C" void kernel_launch(void* const* d_in, const int* in_sizes, int n_in,
                              void* d_out, int out_size)
{
    const float* logits          = (const float*)d_in[0];
    const int*   targets         = (const int*)  d_in[1];
    const int*   logits_lengths  = (const int*)  d_in[2];
    const int*   targets_lengths = (const int*)  d_in[3];
    float*       out             = (float*)      d_out;

    const int B = in_sizes[2];               // 64
    const int S = in_sizes[1] / B;           // 200
    const int T = in_sizes[0] / (B * VDIM);  // 2000

    static int smem_set = 0;
    if (!smem_set) {
        cudaFuncSetAttribute(ctc_fused_kernel,
                             cudaFuncAttributeMaxDynamicSharedMemorySize,
                             SMEM_BYTES);
        smem_set = 1;
    }

    ctc_fused_kernel<<<NALPHA + BMAX, NTHR, SMEM_BYTES>>>(
        logits, targets, logits_lengths, targets_lengths, out, T, S);
}

// round 13
// speedup vs baseline: 1.7718x; 1.7718x over previous
#include <cuda_runtime.h>
#include <cstdint>

// Shape (fixed by setup_inputs): B=64, T=2000, V=256, S=200, L=401
#define NEG2 -1e30f
#define VDIM 256
#define BMAX 64
#define NWIN 4                // 2-step windows per barrier block
#define ROWSPB 8              // rows consumed per barrier block
#define GHOSTL 4              // ghost lanes per warp (1 lane corrupted / window)
#define LPW 28                // real lanes per warp (28*2*4 = 224 pairs >= 201)
#define NTHR 128
#define NSTAGE 32             // cp.async ring stages (32 KB)
#define INVLN2 1.4426950408889634f
#define LN2F   0.6931471805599453f

// Cross-block scratch (device globals: no allocation).
__device__ float g_lsesum[BMAX];
__device__ int   g_flag[BMAX];

__device__ __forceinline__ float ex2f(float x) {
    float y; asm("ex2.approx.f32 %0, %1;" : "=f"(y) : "f"(x)); return y;
}
__device__ __forceinline__ float lg2f(float x) {
    float y; asm("lg2.approx.f32 %0, %1;" : "=f"(y) : "f"(x)); return y;
}

// Composed 2-step CTC window update (log2 domain), 2 pairs per thread.
// Factored form: 7 alpha-ex2 + 4 lg2 in the loop; emission factors
// fb,fl,fh,fm = 2^(e - cmx) precomputed off the critical path.
__device__ __forceinline__ void window_update(
    float& B0, float& L0, float& B1, float& L1,
    float fb, float fl, float fh, float fm,
    float b1, float el1, float eh1, float cmx,
    float g_lo, float g_hi, float g_m1, int lane)
{
    float Lm1 = __shfl_up_sync(0xFFFFFFFFu, L1, 1);
    float Bm1 = __shfl_up_sync(0xFFFFFFFFu, B1, 1);
    float Lm2 = __shfl_up_sync(0xFFFFFFFFu, L0, 1);
    if (lane == 0) { Lm1 = NEG2; Bm1 = NEG2; Lm2 = NEG2; }

    float amax = fmaxf(fmaxf(fmaxf(B0, L0), fmaxf(B1, L1)),
                       fmaxf(fmaxf(Lm1, Bm1), Lm2));
    float M = amax + cmx;

    // 7 alpha exponentials relative to amax (all <= 1).
    float eB0  = ex2f(B0  - amax);
    float eL0  = ex2f(L0  - amax);
    float eB1  = ex2f(B1  - amax);
    float eL1  = ex2f(L1  - amax);
    float eLm1 = ex2f(Lm1 - amax);
    float eBm1 = ex2f(Bm1 - amax);
    float eLm2 = ex2f(Lm2 - amax);

    float Q   = fm * (eLm1 + eBm1 + g_m1 * eLm2);
    float x12 = fb * (eB0 + eLm1);
    float Ys  = fl * (eL0 + eB0 + g_lo * eLm1);
    float z12 = fb * (eB1 + eL0);
    float Us  = fh * (eL1 + eB1 + g_hi * eL0);

    float sB0 = x12 + Q;
    float sL0 = Ys + x12 + g_lo * Q;
    float sB1 = z12 + Ys;
    float sL1 = Us + z12 + g_hi * Ys;

    // Clamp at NEG2: keeps every alpha finite (no NaN from -inf - -inf).
    B0 = fmaxf(M + lg2f(sB0) + b1,  NEG2);
    L0 = fmaxf(M + lg2f(sL0) + el1, NEG2);
    B1 = fmaxf(M + lg2f(sB1) + b1,  NEG2);
    L1 = fmaxf(M + lg2f(sL1) + eh1, NEG2);
}

// ---------------------------------------------------------------------------
// Fused kernel: blocks [0,64) = per-row LSE sums (concurrent with alpha);
// blocks [64,128) = alpha recursion for row b = blockIdx.x - 64.
// ---------------------------------------------------------------------------
__global__ __launch_bounds__(NTHR, 1)
void ctc_fused_kernel(const float* __restrict__ logits,
                      const int*  __restrict__ targets,
                      const int*  __restrict__ logits_lengths,
                      const int*  __restrict__ targets_lengths,
                      float* __restrict__ out,
                      int T, int S)
{
    const int tid  = threadIdx.x;
    const int lane = tid & 31;
    const int w    = tid >> 5;

    __shared__ float  sh_row[NSTAGE][VDIM];
    __shared__ float4 sh_halo[2][4][GHOSTL];
    __shared__ float  sh_fin[2];
    __shared__ float  sh_part[4];

    if (blockIdx.x < BMAX) {
        // ================= LSE block =================
        const int b   = blockIdx.x;
        const int len = __ldg(&logits_lengths[b]);
        const float* __restrict__ rowp = logits + (size_t)b * T * VDIM;
        float acc = 0.0f;
        for (int t = w; t < len; t += 4) {
            const float4* r4 = reinterpret_cast<const float4*>(rowp + (size_t)t * VDIM);
            float4 a = r4[lane], c = r4[lane + 32];
            float s = __expf(a.x)+__expf(a.y)+__expf(a.z)+__expf(a.w)
                    + __expf(c.x)+__expf(c.y)+__expf(c.z)+__expf(c.w);
            #pragma unroll
            for (int o = 16; o; o >>= 1) s += __shfl_xor_sync(0xFFFFFFFFu, s, o);
            if (lane == 0) acc += __logf(s);
        }
        if (lane == 0) sh_part[w] = acc;
        __syncthreads();
        if (tid == 0) {
            g_lsesum[b] = sh_part[0] + sh_part[1] + sh_part[2] + sh_part[3];
            __threadfence();
            g_flag[b] = 1;
        }
        return;
    }

    // ================= alpha block =================
    const int b = blockIdx.x - BMAX;

    const int plo = 2 * (w * LPW + lane - GHOSTL);
    const int phi = plo + 1;
    const bool realln = (lane >= GHOSTL);

    int lblo = 0, lbhi = 0, sklo = 0, skhi = 0;
    if (plo >= 0 && plo < S) {
        lblo = __ldg(&targets[b * S + plo]);
        if (plo >= 1) sklo = (lblo != __ldg(&targets[b * S + plo - 1]));
    }
    if (phi >= 0 && phi < S) {
        lbhi = __ldg(&targets[b * S + phi]);
        skhi = (lbhi != __ldg(&targets[b * S + phi - 1]));
    }
    const float g_lo = sklo ? 1.0f : 0.0f;
    const float g_hi = skhi ? 1.0f : 0.0f;
    float g_m1 = __shfl_up_sync(0xFFFFFFFFu, g_hi, 1);
    if (lane == 0) g_m1 = 0.0f;
    const float pen_lo = sklo ? 0.0f : NEG2;
    const float pen_hi = skhi ? 0.0f : NEG2;

    float B0 = (plo == 0) ? 0.0f : NEG2, L0 = NEG2, B1 = NEG2, L1 = NEG2;

    if (lane >= 32 - GHOSTL)
        sh_halo[0][w][lane - (32 - GHOSTL)] = make_float4(B0, L0, B1, L1);

    const int len = __ldg(&logits_lengths[b]);
    const int W   = len >> 1;
    const int odd = len & 1;
    const float* __restrict__ rowp = logits + (size_t)b * T * VDIM;

    uint32_t s_base = (uint32_t)__cvta_generic_to_shared(&sh_row[0][0]);

    // Prologue: stage rows 0..15 (2 groups of 8); len >= 1500 so all valid.
    {
        #pragma unroll
        for (int g = 0; g < 2; ++g) {
            #pragma unroll
            for (int i = 0; i < ROWSPB; ++i) {
                int st = g * ROWSPB + i;
                uint32_t dst = s_base + (uint32_t)(st * VDIM * 4 + tid * 8);
                const float* src = rowp + (size_t)st * VDIM + tid * 2;
                asm volatile("cp.async.ca.shared.global [%0], [%1], 8;\n"
                             :: "r"(dst), "l"(src));
            }
            asm volatile("cp.async.commit_group;\n");
        }
        asm volatile("cp.async.wait_group 0;\n" ::: "memory");
    }
    __syncthreads();

    // Emissions for block 0 (windows 0..3): factored form.
    float cfb[NWIN], cfl[NWIN], cfh[NWIN], cfm[NWIN],
          cb1[NWIN], cl1[NWIN], ch1[NWIN], cmx[NWIN];
    #pragma unroll
    for (int i = 0; i < NWIN; ++i) {
        const float* r0 = &sh_row[2 * i][0];
        const float* r1 = &sh_row[2 * i + 1][0];
        float b0  = r0[0]    * INVLN2;
        float el0 = r0[lblo] * INVLN2;
        float eh0 = r0[lbhi] * INVLN2;
        float em0 = __shfl_up_sync(0xFFFFFFFFu, eh0, 1);
        float mx  = fmaxf(fmaxf(b0, el0), fmaxf(eh0, em0));
        cmx[i] = mx;
        cfb[i] = ex2f(b0  - mx);
        cfl[i] = ex2f(el0 - mx);
        cfh[i] = ex2f(eh0 - mx);
        cfm[i] = ex2f(em0 - mx);
        cb1[i] = r1[0]    * INVLN2;
        cl1[i] = r1[lblo] * INVLN2;
        ch1[i] = r1[lbhi] * INVLN2;
    }

    const int nblk = (W + NWIN - 1) / NWIN;
    int par = 0;
    for (int blk = 0; blk < nblk; ++blk) {
        const int tb = blk * ROWSPB;

        // Stage rows tb+16..tb+23; resident guaranteed through tb+15.
        {
            #pragma unroll
            for (int i = 0; i < ROWSPB; ++i) {
                const int tn = tb + 2 * ROWSPB + i;
                if (tn < len) {
                    uint32_t dst = s_base +
                        (uint32_t)((tn & (NSTAGE - 1)) * VDIM * 4 + tid * 8);
                    const float* src = rowp + (size_t)tn * VDIM + tid * 2;
                    asm volatile("cp.async.ca.shared.global [%0], [%1], 8;\n"
                                 :: "r"(dst), "l"(src));
                }
            }
            asm volatile("cp.async.commit_group;\n");
            asm volatile("cp.async.wait_group 1;\n" ::: "memory");
        }
        __syncthreads();

        if (lane < GHOSTL && w > 0) {
            float4 h = sh_halo[par][w - 1][lane];
            B0 = h.x; L0 = h.y; B1 = h.z; L1 = h.w;
        }

        // Gather + factor next block's emissions (rows tb+8..tb+15).
        float nfb[NWIN], nfl[NWIN], nfh[NWIN], nfm[NWIN],
              nb1[NWIN], nl1[NWIN], nh1[NWIN], nmx[NWIN];
        #pragma unroll
        for (int i = 0; i < NWIN; ++i) {
            const int r0i = min(tb + ROWSPB + 2 * i,     len - 1);
            const int r1i = min(tb + ROWSPB + 2 * i + 1, len - 1);
            const float* r0 = &sh_row[r0i & (NSTAGE - 1)][0];
            const float* r1 = &sh_row[r1i & (NSTAGE - 1)][0];
            float b0  = r0[0]    * INVLN2;
            float el0 = r0[lblo] * INVLN2;
            float eh0 = r0[lbhi] * INVLN2;
            float em0 = __shfl_up_sync(0xFFFFFFFFu, eh0, 1);
            float mx  = fmaxf(fmaxf(b0, el0), fmaxf(eh0, em0));
            nmx[i] = mx;
            nfb[i] = ex2f(b0  - mx);
            nfl[i] = ex2f(el0 - mx);
            nfh[i] = ex2f(eh0 - mx);
            nfm[i] = ex2f(em0 - mx);
            nb1[i] = r1[0]    * INVLN2;
            nl1[i] = r1[lblo] * INVLN2;
            nh1[i] = r1[lbhi] * INVLN2;
        }

        const int wbase = blk * NWIN;
        if (wbase + NWIN <= W) {
            #pragma unroll
            for (int i = 0; i < NWIN; ++i)
                window_update(B0, L0, B1, L1,
                              cfb[i], cfl[i], cfh[i], cfm[i],
                              cb1[i], cl1[i], ch1[i], cmx[i],
                              g_lo, g_hi, g_m1, lane);
        } else {
            #pragma unroll
            for (int i = 0; i < NWIN; ++i) {
                float tB0 = B0, tL0 = L0, tB1 = B1, tL1 = L1;
                window_update(tB0, tL0, tB1, tL1,
                              cfb[i], cfl[i], cfh[i], cfm[i],
                              cb1[i], cl1[i], ch1[i], cmx[i],
                              g_lo, g_hi, g_m1, lane);
                const bool act = (wbase + i) < W;
                B0 = act ? tB0 : B0;  L0 = act ? tL0 : L0;
                B1 = act ? tB1 : B1;  L1 = act ? tL1 : L1;
            }
        }

        if (lane >= 32 - GHOSTL)
            sh_halo[par ^ 1][w][lane - (32 - GHOSTL)] = make_float4(B0, L0, B1, L1);
        par ^= 1;

        #pragma unroll
        for (int i = 0; i < NWIN; ++i) {
            cfb[i] = nfb[i]; cfl[i] = nfl[i]; cfh[i] = nfh[i]; cfm[i] = nfm[i];
            cb1[i] = nb1[i]; cl1[i] = nl1[i]; ch1[i] = nh1[i]; cmx[i] = nmx[i];
        }
    }

    __syncthreads();   // final halo stores visible

    if (odd) {
        // One plain step for t = len-1 (maxes clamped: -inf/-inf safe).
        if (lane < GHOSTL && w > 0) {
            float4 h = sh_halo[par][w - 1][lane];
            B0 = h.x; L0 = h.y; B1 = h.z; L1 = h.w;
        }
        const float* rr = &sh_row[(len - 1) & (NSTAGE - 1)][0];
        const float eb = rr[0]    * INVLN2;
        const float el = rr[lblo] * INVLN2;
        const float eh = rr[lbhi] * INVLN2;

        float pL = __shfl_up_sync(0xFFFFFFFFu, L1, 1);
        if (lane == 0) pL = NEG2;

        float m0  = fmaxf(fmaxf(B0, pL), -1e30f);
        float nB0 = m0 + lg2f(ex2f(B0 - m0) + ex2f(pL - m0)) + eb;
        float t3  = pL + pen_lo;
        float m1  = fmaxf(fmaxf(fmaxf(L0, B0), t3), -1e30f);
        float nL0 = m1 + lg2f(ex2f(L0 - m1) + ex2f(B0 - m1) + ex2f(t3 - m1)) + el;

        float m2  = fmaxf(fmaxf(B1, L0), -1e30f);
        float nB1 = m2 + lg2f(ex2f(B1 - m2) + ex2f(L0 - m2)) + eb;
        float t3h = L0 + pen_hi;
        float m3  = fmaxf(fmaxf(fmaxf(L1, B1), t3h), -1e30f);
        float nL1 = m3 + lg2f(ex2f(L1 - m3) + ex2f(B1 - m3) + ex2f(t3h - m3)) + eh;

        B0 = nB0; L0 = nL0; B1 = nB1; L1 = nL1;
    }

    // ---- epilogue ----
    const int tl = __ldg(&targets_lengths[b]);
    if (realln) {
        if (plo == tl - 1) sh_fin[0] = L0;   // state 2*tl - 1
        if (phi == tl - 1) sh_fin[0] = L1;
        if (plo == tl)     sh_fin[1] = B0;   // state 2*tl
        if (phi == tl)     sh_fin[1] = B1;
    }
    __syncthreads();

    if (tid == 0) {
        while (((volatile int*)g_flag)[b] == 0) { }
        const float ls = *((volatile float*)&g_lsesum[b]);
        const float f1 = sh_fin[0], f2 = sh_fin[1];   // log2 units
        const float mm = fmaxf(fmaxf(f1, f2), -1e30f);
        const float lae = mm + lg2f(ex2f(f1 - mm) + ex2f(f2 - mm));
        out[b] = ls - LN2F * lae;
    }
}

// ---------------------------------------------------------------------------
// Launch: single fused kernel, 128 blocks (64 lse + 64 alpha).
// ---------------------------------------------------------------------------
extern "C" void kernel_launch(void* const* d_in, const int* in_sizes, int n_in,
                              void* d_out, int out_size)
{
    const float* logits          = (const float*)d_in[0];
    const int*   targets         = (const int*)  d_in[1];
    const int*   logits_lengths  = (const int*)  d_in[2];
    const int*   targets_lengths = (const int*)  d_in[3];
    float*       out             = (float*)      d_out;

    const int B = in_sizes[2];               // 64
    const int S = in_sizes[1] / B;           // 200
    const int T = in_sizes[0] / (B * VDIM);  // 2000

    ctc_fused_kernel<<<2 * B, NTHR>>>(logits, targets, logits_lengths,
                                      targets_lengths, out, T, S);
}